// round 7
// baseline (speedup 1.0000x reference)
#include <cuda_runtime.h>
#include <cstdint>

#define NN 8192
#define IN_F 256
#define OUT_F 64
#define LEAK 0.2f

// ---------------- scratch (device globals; no runtime allocation) ----------
__device__ float g_h[NN * OUT_F];   // tf32-rounded h, row-major [j][f]
__device__ float g_si[NN];
__device__ float g_sj[NN];
__device__ float g_gamma[NN];
__device__ float g_beta[NN];

// ---------------- helpers ---------------------------------------------------
__device__ __forceinline__ float to_tf32(float x) {
    uint32_t u;
    asm("cvt.rna.tf32.f32 %0, %1;" : "=r"(u) : "f"(x));
    return __uint_as_float(u);
}

__device__ __forceinline__ uint32_t smem_u32(const void* p) {
    uint32_t a;
    asm("{ .reg .u64 t; cvta.to.shared.u64 t, %1; cvt.u32.u64 %0, t; }"
        : "=r"(a) : "l"(p));
    return a;
}

__device__ __forceinline__ void mma_tf32(float& c0, float& c1, float& c2, float& c3,
                                         uint32_t a0, uint32_t a1, uint32_t a2, uint32_t a3,
                                         uint32_t b0, uint32_t b1)
{
    asm volatile("mma.sync.aligned.m16n8k8.row.col.f32.tf32.tf32.f32 "
                 "{%0,%1,%2,%3}, {%4,%5,%6,%7}, {%8,%9}, {%0,%1,%2,%3};"
                 : "+f"(c0), "+f"(c1), "+f"(c2), "+f"(c3)
                 : "r"(a0), "r"(a1), "r"(a2), "r"(a3), "r"(b0), "r"(b1));
}

#define CP_ASYNC16(dst, src) \
    asm volatile("cp.async.cg.shared.global [%0], [%1], 16;" :: "r"(dst), "l"(src) : "memory")
#define CP_COMMIT() asm volatile("cp.async.commit_group;" ::: "memory")
#define CP_WAIT0()  asm volatile("cp.async.wait_group 0;" ::: "memory")

// ============================================================================
// Kernel 1: h = x @ W ; s_i, s_j, gamma, beta (exact fp32); g_h tf32-rounded
// 128 blocks x 512 threads, 64 rows/block. xs padded: kills 4-way bank conflict.
// ============================================================================
#define XSTR 260
#define PREP_SMEM ((IN_F * OUT_F + 64 * XSTR + 4 * OUT_F) * 4)

__global__ __launch_bounds__(512, 1) void prep_kernel(
    const float* __restrict__ x, const float* __restrict__ W,
    const float* __restrict__ a_i, const float* __restrict__ a_j,
    const float* __restrict__ w_g, const float* __restrict__ w_b)
{
    extern __shared__ float sm[];
    float* Ws = sm;                          // [256][64]
    float* xs = Ws + IN_F * OUT_F;           // [64][XSTR]
    float* vs = xs + 64 * XSTR;              // 4 x [64]

    const int t = threadIdx.x;
    const int row0 = blockIdx.x * 64;

    for (int i = t; i < IN_F * OUT_F / 4; i += 512)
        ((float4*)Ws)[i] = ((const float4*)W)[i];
    for (int c = t; c < 64 * 64; c += 512) {          // 64 rows x 64 float4
        const int row = c >> 6, k4 = c & 63;
        *(float4*)&xs[row * XSTR + k4 * 4] =
            ((const float4*)(x + (size_t)(row0 + row) * IN_F))[k4];
    }
    if (t < OUT_F) {
        vs[t]             = a_i[t];
        vs[OUT_F + t]     = a_j[t];
        vs[2 * OUT_F + t] = w_g[t];
        vs[3 * OUT_F + t] = w_b[t];
    }
    __syncthreads();

    const int row = t >> 3;        // 0..63
    const int fg  = t & 7;
    const int f0  = fg * 8;

    float acc[8];
#pragma unroll
    for (int i = 0; i < 8; i++) acc[i] = 0.0f;

    const float* xr = xs + row * XSTR;
#pragma unroll 4
    for (int k = 0; k < IN_F; k++) {
        const float xv = xr[k];
        const float* wr = Ws + k * OUT_F + f0;
#pragma unroll
        for (int ff = 0; ff < 8; ff++) acc[ff] = fmaf(xv, wr[ff], acc[ff]);
    }

    const int grow = row0 + row;
    float4* hp = (float4*)(g_h + (size_t)grow * OUT_F + f0);
    hp[0] = make_float4(to_tf32(acc[0]), to_tf32(acc[1]), to_tf32(acc[2]), to_tf32(acc[3]));
    hp[1] = make_float4(to_tf32(acc[4]), to_tf32(acc[5]), to_tf32(acc[6]), to_tf32(acc[7]));

    float psi = 0.f, psj = 0.f, pg = 0.f, pb = 0.f;
#pragma unroll
    for (int ff = 0; ff < 8; ff++) {
        const float a = acc[ff];
        psi = fmaf(a, vs[f0 + ff], psi);
        psj = fmaf(a, vs[OUT_F + f0 + ff], psj);
        pg  = fmaf(a, vs[2 * OUT_F + f0 + ff], pg);
        pb  = fmaf(a, vs[3 * OUT_F + f0 + ff], pb);
    }
#pragma unroll
    for (int off = 4; off > 0; off >>= 1) {
        psi += __shfl_down_sync(0xffffffffu, psi, off);
        psj += __shfl_down_sync(0xffffffffu, psj, off);
        pg  += __shfl_down_sync(0xffffffffu, pg,  off);
        pb  += __shfl_down_sync(0xffffffffu, pb,  off);
    }
    if (fg == 0) {
        g_si[grow]    = psi;
        g_sj[grow]    = psj;
        g_gamma[grow] = pg + 1.0f;
        g_beta[grow]  = pb;
    }
}

// ============================================================================
// Kernel 2: fused masked softmax-attention via mma.sync tf32 + FiLM.
// 128 blocks x 1024 threads (32 warps). Block = 64 rows, j-tile BN=128.
// Warp grid: kh = wid&7 (K-eighth) x mh = wid>>3 (M-quarter, 16 rows).
// 32 accums/thread -> fits 64-reg budget at occ 50%.
// cp.async double-buffered adj+h; sj persistent in SMEM.
// ============================================================================
#define BN   128
#define ASTR 132
#define HSTR 72
#define PSTR 68

#define OFF_SJ  0                        // 8192 floats
#define OFF_H   8192                     // 2 x 128 x 72 = 18432
#define OFF_ADJ 26624                    // 2 x 64 x 132 = 16896 (ints)
#define OFF_W   43520                    // 64 x 132 = 8448
#define OFF_DEN 51968                    // 64
#define SMEM_FLOATS 52032
#define ATTN_SMEM (SMEM_FLOATS * 4)      // 208128 B
// epilogue partials [8][64][68] = 34816 floats overlay at offset 0

__global__ __launch_bounds__(1024, 1) void attn_kernel(
    const int* __restrict__ adj, float* __restrict__ out)
{
    extern __shared__ float sf[];
    const uint32_t sbase = smem_u32(sf);

    const int t    = threadIdx.x;
    const int lane = t & 31;
    const int wid  = t >> 5;
    const int g    = lane >> 2;   // mma groupID
    const int tg   = lane & 3;    // mma threadID-in-group
    const int i0   = blockIdx.x * 64;

    const int r  = t >> 4;        // gen row 0..63
    const int cc = t & 15;        // gen chunk lane 0..15

    const int kh = wid & 7;       // K-eighth
    const int mh = wid >> 3;      // M-quarter (16 rows)

    const float si_r = g_si[i0 + r];
    const char* adj_row = (const char*)(adj + (size_t)(i0 + r) * NN);

    // hoisted per-thread addresses (bytes)
    const uint32_t adj_dst0 = sbase + (OFF_ADJ + r * ASTR + cc * 4) * 4;
    const int hc  = t;                       // h chunk ids: t, t+1024
    const int hk0 = hc >> 4,   hn0 = hc & 15;
    const int hk1 = (hc + 1024) >> 4, hn1 = (hc + 1024) & 15;
    const uint32_t h_dst0 = sbase + (OFF_H + hk0 * HSTR + hn0 * 4) * 4;
    const uint32_t h_dst1 = sbase + (OFF_H + hk1 * HSTR + hn1 * 4) * 4;
    const uint32_t ADJ_BUFB = 64 * ASTR * 4;     // byte stride between adj buffers
    const uint32_t H_BUFB   = 128 * HSTR * 4;

    // ---- prologue: sj + tile 0 via cp.async ----
    {
#pragma unroll
        for (int it = 0; it < 2; it++) {
            const int c = t + it * 1024;
            CP_ASYNC16(sbase + (OFF_SJ + c * 4) * 4, (const char*)g_sj + c * 16);
        }
        CP_ASYNC16(adj_dst0,             adj_row + cc * 16);
        CP_ASYNC16(adj_dst0 + 16 * 16,   adj_row + (cc + 16) * 16);
        CP_ASYNC16(h_dst0, (const char*)g_h + hc * 16);
        CP_ASYNC16(h_dst1, (const char*)g_h + (hc + 1024) * 16);
        CP_COMMIT();
    }

    float acc[8][4];
#pragma unroll
    for (int b = 0; b < 8; b++)
#pragma unroll
        for (int c = 0; c < 4; c++) acc[b][c] = 0.0f;
    float dsum = 0.0f;

    for (int tile = 0; tile < NN / BN; tile++) {
        const int buf = tile & 1;
        CP_WAIT0();
        __syncthreads();

        // ---- issue next tile's cp.async ----
        if (tile + 1 < NN / BN) {
            const uint32_t nb = (buf ^ 1);
            const int j1 = (tile + 1) * BN;
            const char* asrc = adj_row + (size_t)j1 * 4;
            CP_ASYNC16(adj_dst0 + nb * ADJ_BUFB,           asrc + cc * 16);
            CP_ASYNC16(adj_dst0 + nb * ADJ_BUFB + 16 * 16, asrc + (cc + 16) * 16);
            const char* hsrc = (const char*)(g_h + (size_t)j1 * OUT_F);
            CP_ASYNC16(h_dst0 + nb * H_BUFB, hsrc + hc * 16);
            CP_ASYNC16(h_dst1 + nb * H_BUFB, hsrc + (hc + 1024) * 16);
            CP_COMMIT();
        }

        // ---- gen: w = adj ? exp(lrelu(si + sj)) : 0  (all from SMEM) ----
        {
            const int4*   arow = (const int4*)(sf + OFF_ADJ + buf * 64 * ASTR + r * ASTR);
            const float4* sjr  = (const float4*)(sf + OFF_SJ + tile * BN);
            float4* wrow = (float4*)(sf + OFF_W + r * ASTR);
#pragma unroll
            for (int q = 0; q < 2; q++) {
                const int gi = cc + q * 16;
                const int4   a = arow[gi];
                const float4 s = sjr[gi];
                float w0, w1, w2, w3, e;
                e = si_r + s.x; e = e > 0.f ? e : LEAK * e; w0 = a.x ? __expf(e) : 0.f;
                e = si_r + s.y; e = e > 0.f ? e : LEAK * e; w1 = a.y ? __expf(e) : 0.f;
                e = si_r + s.z; e = e > 0.f ? e : LEAK * e; w2 = a.z ? __expf(e) : 0.f;
                e = si_r + s.w; e = e > 0.f ? e : LEAK * e; w3 = a.w ? __expf(e) : 0.f;
                dsum += (w0 + w1) + (w2 + w3);
                wrow[gi] = make_float4(to_tf32(w0), to_tf32(w1), to_tf32(w2), to_tf32(w3));
            }
        }
        __syncthreads();

        // ---- mma: warp (kh, mh): rows mh*16..+15, k-cols kh*16..+15 ----
        {
            const uint32_t* wsu = (const uint32_t*)(sf + OFF_W);
            const uint32_t* hsu = (const uint32_t*)(sf + OFF_H + buf * 128 * HSTR);
#pragma unroll
            for (int kc = 0; kc < 2; kc++) {
                const int k0 = kh * 16 + kc * 8;
                const uint32_t* wp = wsu + (mh * 16 + g) * ASTR + k0 + tg;
                uint32_t ka0 = wp[0];
                uint32_t ka1 = wp[8 * ASTR];
                uint32_t ka2 = wp[4];
                uint32_t ka3 = wp[8 * ASTR + 4];
#pragma unroll
                for (int nt = 0; nt < 8; nt++) {
                    const uint32_t b0 = hsu[(k0 + tg) * HSTR + nt * 8 + g];
                    const uint32_t b1 = hsu[(k0 + tg + 4) * HSTR + nt * 8 + g];
                    float* c = acc[nt];
                    mma_tf32(c[0], c[1], c[2], c[3], ka0, ka1, ka2, ka3, b0, b1);
                }
            }
        }
    }

    __syncthreads();   // all mma done; smem reusable for partials

    // ---- stage K-split partials + denominators ----
    {
        float* part = sf + kh * (64 * PSTR);
        const int m = mh * 16 + g;
#pragma unroll
        for (int nt = 0; nt < 8; nt++) {
            const float* c = acc[nt];
            const int n = nt * 8 + tg * 2;
            *(float2*)&part[m * PSTR + n]       = make_float2(c[0], c[1]);
            *(float2*)&part[(m + 8) * PSTR + n] = make_float2(c[2], c[3]);
        }
    }
    dsum += __shfl_down_sync(0xffffffffu, dsum, 8);
    dsum += __shfl_down_sync(0xffffffffu, dsum, 4);
    dsum += __shfl_down_sync(0xffffffffu, dsum, 2);
    dsum += __shfl_down_sync(0xffffffffu, dsum, 1);
    if (cc == 0) sf[OFF_DEN + r] = dsum;     // lanes 0 and 16
    __syncthreads();

    // ---- reduce 8 partials + FiLM + store (4 outputs/thread) ----
    {
        const int m  = t >> 4;
        const int n0 = (t & 15) * 4;
        const float inv = 1.0f / sf[OFF_DEN + m];
        const float gm  = g_gamma[i0 + m];
        const float bt  = g_beta[i0 + m];
        float sx = 0.f, sy = 0.f, sz = 0.f, sw = 0.f;
#pragma unroll
        for (int w = 0; w < 8; w++) {
            const float4 p = *(const float4*)&sf[w * (64 * PSTR) + m * PSTR + n0];
            sx += p.x; sy += p.y; sz += p.z; sw += p.w;
        }
        *(float4*)(out + (size_t)(i0 + m) * OUT_F + n0) =
            make_float4(fmaf(gm, sx * inv, bt), fmaf(gm, sy * inv, bt),
                        fmaf(gm, sz * inv, bt), fmaf(gm, sw * inv, bt));
    }
}

// ============================================================================
extern "C" void kernel_launch(void* const* d_in, const int* in_sizes, int n_in,
                              void* d_out, int out_size)
{
    const float* x   = (const float*)d_in[0];
    const int*   adj = (const int*)d_in[1];
    const float* W   = (const float*)d_in[2];
    const float* a_i = (const float*)d_in[3];
    const float* a_j = (const float*)d_in[4];
    const float* w_g = (const float*)d_in[5];
    const float* w_b = (const float*)d_in[6];
    float* out = (float*)d_out;

    cudaFuncSetAttribute(prep_kernel, cudaFuncAttributeMaxDynamicSharedMemorySize, PREP_SMEM);
    cudaFuncSetAttribute(attn_kernel, cudaFuncAttributeMaxDynamicSharedMemorySize, ATTN_SMEM);

    prep_kernel<<<NN / 64, 512, PREP_SMEM>>>(x, W, a_i, a_j, w_g, w_b);
    attn_kernel<<<NN / 64, 1024, ATTN_SMEM>>>(adj, out);
}

// round 8
// speedup vs baseline: 1.0458x; 1.0458x over previous
#include <cuda_runtime.h>
#include <cstdint>

#define NN 8192
#define IN_F 256
#define OUT_F 64
#define LEAK 0.2f

// ---------------- scratch (device globals; no runtime allocation) ----------
__device__ float  g_h[NN * OUT_F];     // tf32-rounded h, row-major [j][f]
__device__ float4 g_rowEFG[NN];        // (exp(si), exp(.2 si), exp(-si), 0)
__device__ float2 g_ef[NN];            // (exp(sj), exp(.2 sj))
__device__ float  g_gamma[NN];
__device__ float  g_beta[NN];

// ---------------- helpers ---------------------------------------------------
__device__ __forceinline__ float to_tf32(float x) {
    uint32_t u;
    asm("cvt.rna.tf32.f32 %0, %1;" : "=r"(u) : "f"(x));
    return __uint_as_float(u);
}

__device__ __forceinline__ uint32_t smem_u32(const void* p) {
    uint32_t a;
    asm("{ .reg .u64 t; cvta.to.shared.u64 t, %1; cvt.u32.u64 %0, t; }"
        : "=r"(a) : "l"(p));
    return a;
}

__device__ __forceinline__ void mma_tf32(float& c0, float& c1, float& c2, float& c3,
                                         uint32_t a0, uint32_t a1, uint32_t a2, uint32_t a3,
                                         uint32_t b0, uint32_t b1)
{
    asm volatile("mma.sync.aligned.m16n8k8.row.col.f32.tf32.tf32.f32 "
                 "{%0,%1,%2,%3}, {%4,%5,%6,%7}, {%8,%9}, {%0,%1,%2,%3};"
                 : "+f"(c0), "+f"(c1), "+f"(c2), "+f"(c3)
                 : "r"(a0), "r"(a1), "r"(a2), "r"(a3), "r"(b0), "r"(b1));
}

#define CP_ASYNC16(dst, src) \
    asm volatile("cp.async.cg.shared.global [%0], [%1], 16;" :: "r"(dst), "l"(src) : "memory")
#define CP_COMMIT() asm volatile("cp.async.commit_group;" ::: "memory")
#define CP_WAIT0()  asm volatile("cp.async.wait_group 0;" ::: "memory")

// ============================================================================
// Kernel 1: h = x @ W ; E/F/G factors, gamma, beta ; g_h tf32-rounded
// 256 blocks x 512 threads, 32 rows/block (2 blocks/SM).
// ============================================================================
#define XSTR 260
#define PREP_SMEM ((IN_F * OUT_F + 32 * XSTR + 4 * OUT_F) * 4)

__global__ __launch_bounds__(512, 2) void prep_kernel(
    const float* __restrict__ x, const float* __restrict__ W,
    const float* __restrict__ a_i, const float* __restrict__ a_j,
    const float* __restrict__ w_g, const float* __restrict__ w_b)
{
    extern __shared__ float sm[];
    float* Ws = sm;                          // [256][64] (float4-read)
    float* xs = Ws + IN_F * OUT_F;           // [32][XSTR]
    float* vs = xs + 32 * XSTR;              // 4 x [64]

    const int t = threadIdx.x;
    const int row0 = blockIdx.x * 32;

    for (int i = t; i < IN_F * OUT_F / 4; i += 512)
        ((float4*)Ws)[i] = ((const float4*)W)[i];
    for (int c = t; c < 32 * 64; c += 512) {          // 32 rows x 64 float4
        const int row = c >> 6, k4 = c & 63;
        *(float4*)&xs[row * XSTR + k4 * 4] =
            ((const float4*)(x + (size_t)(row0 + row) * IN_F))[k4];
    }
    if (t < OUT_F) {
        vs[t]             = a_i[t];
        vs[OUT_F + t]     = a_j[t];
        vs[2 * OUT_F + t] = w_g[t];
        vs[3 * OUT_F + t] = w_b[t];
    }
    __syncthreads();

    const int row = t >> 4;        // 0..31
    const int fg  = t & 15;        // 0..15
    const int f0  = fg * 4;

    float4 acc = make_float4(0.f, 0.f, 0.f, 0.f);
    const float*  xr  = xs + row * XSTR;
    const float4* Ws4 = (const float4*)Ws;
#pragma unroll 8
    for (int k = 0; k < IN_F; k++) {
        const float xv = xr[k];
        const float4 w4 = Ws4[k * 16 + fg];
        acc.x = fmaf(xv, w4.x, acc.x);
        acc.y = fmaf(xv, w4.y, acc.y);
        acc.z = fmaf(xv, w4.z, acc.z);
        acc.w = fmaf(xv, w4.w, acc.w);
    }

    const int grow = row0 + row;
    *(float4*)(g_h + (size_t)grow * OUT_F + f0) =
        make_float4(to_tf32(acc.x), to_tf32(acc.y), to_tf32(acc.z), to_tf32(acc.w));

    float psi = acc.x * vs[f0]     + acc.y * vs[f0 + 1]     + acc.z * vs[f0 + 2]     + acc.w * vs[f0 + 3];
    float psj = acc.x * vs[64+f0]  + acc.y * vs[64+f0 + 1]  + acc.z * vs[64+f0 + 2]  + acc.w * vs[64+f0 + 3];
    float pg  = acc.x * vs[128+f0] + acc.y * vs[128+f0 + 1] + acc.z * vs[128+f0 + 2] + acc.w * vs[128+f0 + 3];
    float pb  = acc.x * vs[192+f0] + acc.y * vs[192+f0 + 1] + acc.z * vs[192+f0 + 2] + acc.w * vs[192+f0 + 3];
#pragma unroll
    for (int off = 8; off > 0; off >>= 1) {
        psi += __shfl_down_sync(0xffffffffu, psi, off, 16);
        psj += __shfl_down_sync(0xffffffffu, psj, off, 16);
        pg  += __shfl_down_sync(0xffffffffu, pg,  off, 16);
        pb  += __shfl_down_sync(0xffffffffu, pb,  off, 16);
    }
    if (fg == 0) {
        g_rowEFG[grow] = make_float4(__expf(psi), __expf(LEAK * psi), __expf(-psi), 0.f);
        g_ef[grow]     = make_float2(__expf(psj), __expf(LEAK * psj));
        g_gamma[grow]  = pg + 1.0f;
        g_beta[grow]   = pb;
    }
}

// ============================================================================
// Kernel 2: fused masked softmax-attention via mma.sync tf32 + FiLM.
// 128 blocks x 1024 threads (32 warps). Block = 64 rows, j-tile BN=128.
// NO exp in the hot loop: w = adj ? (Ej>Gi ? Ei*Ej : Fi*Fj) : 0.
// cp.async double-buffered adj + h + EF tiles.
// Warp grid: kh = wid&7 (K-eighth) x mh = wid>>3 (M-quarter); 32 accums/thread.
// ============================================================================
#define BN   128
#define ASTR 132
#define HSTR 72
#define PSTR 68

#define OFF_H   0                        // 2 x 128 x 72 = 18432 floats
#define OFF_ADJ 18432                    // 2 x 64 x 132 = 16896 (ints)
#define OFF_W   35328                    // 64 x 132 = 8448
#define OFF_EF  43776                    // 2 x 128 x 2 = 512
#define OFF_DEN 44288                    // 64
#define SMEM_FLOATS 44352
#define ATTN_SMEM (SMEM_FLOATS * 4)      // 177408 B
// epilogue partials [8][64][68] = 34816 floats overlay at offset 0

__global__ __launch_bounds__(1024, 1) void attn_kernel(
    const int* __restrict__ adj, float* __restrict__ out)
{
    extern __shared__ float sf[];
    const uint32_t sbase = smem_u32(sf);

    const int t    = threadIdx.x;
    const int lane = t & 31;
    const int wid  = t >> 5;
    const int g    = lane >> 2;   // mma groupID
    const int tg   = lane & 3;    // mma threadID-in-group
    const int i0   = blockIdx.x * 64;

    const int r  = t >> 4;        // gen row 0..63
    const int cc = t & 15;        // gen chunk lane 0..15

    const int kh = wid & 7;       // K-eighth
    const int mh = wid >> 3;      // M-quarter (16 rows)

    const float4 efg = g_rowEFG[i0 + r];
    const float Ei = efg.x, Fi = efg.y, Gi = efg.z;
    const char* adj_row = (const char*)(adj + (size_t)(i0 + r) * NN);

    // hoisted per-thread addresses (bytes)
    const uint32_t adj_dst0 = sbase + (OFF_ADJ + r * ASTR + cc * 4) * 4;
    const int hc  = t;
    const int hk0 = hc >> 4,          hn0 = hc & 15;
    const int hk1 = (hc + 1024) >> 4, hn1 = (hc + 1024) & 15;
    const uint32_t h_dst0 = sbase + (OFF_H + hk0 * HSTR + hn0 * 4) * 4;
    const uint32_t h_dst1 = sbase + (OFF_H + hk1 * HSTR + hn1 * 4) * 4;
    const uint32_t ef_dst = sbase + (OFF_EF + t * 4) * 4;   // t<64 only
    const uint32_t ADJ_BUFB = 64 * ASTR * 4;
    const uint32_t H_BUFB   = 128 * HSTR * 4;
    const uint32_t EF_BUFB  = 256 * 4;

    // ---- prologue: tile 0 (adj, h, EF) via cp.async ----
    {
        CP_ASYNC16(adj_dst0,           adj_row + cc * 16);
        CP_ASYNC16(adj_dst0 + 16 * 16, adj_row + (cc + 16) * 16);
        CP_ASYNC16(h_dst0, (const char*)g_h + hc * 16);
        CP_ASYNC16(h_dst1, (const char*)g_h + (hc + 1024) * 16);
        if (t < 64) CP_ASYNC16(ef_dst, (const char*)g_ef + t * 16);
        CP_COMMIT();
    }

    float acc[8][4];
#pragma unroll
    for (int b = 0; b < 8; b++)
#pragma unroll
        for (int c = 0; c < 4; c++) acc[b][c] = 0.0f;
    float dsum = 0.0f;

    for (int tile = 0; tile < NN / BN; tile++) {
        const int buf = tile & 1;
        CP_WAIT0();
        __syncthreads();

        // ---- issue next tile's cp.async ----
        if (tile + 1 < NN / BN) {
            const uint32_t nb = (buf ^ 1);
            const int j1 = (tile + 1) * BN;
            const char* asrc = adj_row + (size_t)j1 * 4;
            CP_ASYNC16(adj_dst0 + nb * ADJ_BUFB,           asrc + cc * 16);
            CP_ASYNC16(adj_dst0 + nb * ADJ_BUFB + 16 * 16, asrc + (cc + 16) * 16);
            const char* hsrc = (const char*)(g_h + (size_t)j1 * OUT_F);
            CP_ASYNC16(h_dst0 + nb * H_BUFB, hsrc + hc * 16);
            CP_ASYNC16(h_dst1 + nb * H_BUFB, hsrc + (hc + 1024) * 16);
            if (t < 64) CP_ASYNC16(ef_dst + nb * EF_BUFB,
                                   (const char*)(g_ef + j1) + t * 16);
            CP_COMMIT();
        }

        // ---- gen: w = adj ? (Ej>Gi ? Ei*Ej : Fi*Fj) : 0  (no exp!) ----
        {
            const int4*   arow = (const int4*)(sf + OFF_ADJ + buf * 64 * ASTR + r * ASTR);
            const float4* efr  = (const float4*)(sf + OFF_EF + buf * 256);
            float4* wrow = (float4*)(sf + OFF_W + r * ASTR);
#pragma unroll
            for (int q = 0; q < 2; q++) {
                const int gi = cc + q * 16;
                const int4   a   = arow[gi];
                const float4 e01 = efr[gi * 2];       // (E0,F0,E1,F1)
                const float4 e23 = efr[gi * 2 + 1];   // (E2,F2,E3,F3)
                float w0, w1, w2, w3;
                { const bool p = e01.x > Gi; w0 = (p ? Ei : Fi) * (p ? e01.x : e01.y); w0 = a.x ? w0 : 0.f; }
                { const bool p = e01.z > Gi; w1 = (p ? Ei : Fi) * (p ? e01.z : e01.w); w1 = a.y ? w1 : 0.f; }
                { const bool p = e23.x > Gi; w2 = (p ? Ei : Fi) * (p ? e23.x : e23.y); w2 = a.z ? w2 : 0.f; }
                { const bool p = e23.z > Gi; w3 = (p ? Ei : Fi) * (p ? e23.z : e23.w); w3 = a.w ? w3 : 0.f; }
                dsum += (w0 + w1) + (w2 + w3);
                wrow[gi] = make_float4(to_tf32(w0), to_tf32(w1), to_tf32(w2), to_tf32(w3));
            }
        }
        __syncthreads();

        // ---- mma: warp (kh, mh): rows mh*16..+15, k-cols kh*16..+15 ----
        {
            const uint32_t* wsu = (const uint32_t*)(sf + OFF_W);
            const uint32_t* hsu = (const uint32_t*)(sf + OFF_H + buf * 128 * HSTR);
#pragma unroll
            for (int kc = 0; kc < 2; kc++) {
                const int k0 = kh * 16 + kc * 8;
                const uint32_t* wp = wsu + (mh * 16 + g) * ASTR + k0 + tg;
                uint32_t ka0 = wp[0];
                uint32_t ka1 = wp[8 * ASTR];
                uint32_t ka2 = wp[4];
                uint32_t ka3 = wp[8 * ASTR + 4];
#pragma unroll
                for (int nt = 0; nt < 8; nt++) {
                    const uint32_t b0 = hsu[(k0 + tg) * HSTR + nt * 8 + g];
                    const uint32_t b1 = hsu[(k0 + tg + 4) * HSTR + nt * 8 + g];
                    float* c = acc[nt];
                    mma_tf32(c[0], c[1], c[2], c[3], ka0, ka1, ka2, ka3, b0, b1);
                }
            }
        }
    }

    __syncthreads();   // all mma done; smem reusable for partials

    // ---- stage K-split partials + denominators ----
    {
        float* part = sf + kh * (64 * PSTR);
        const int m = mh * 16 + g;
#pragma unroll
        for (int nt = 0; nt < 8; nt++) {
            const float* c = acc[nt];
            const int n = nt * 8 + tg * 2;
            *(float2*)&part[m * PSTR + n]       = make_float2(c[0], c[1]);
            *(float2*)&part[(m + 8) * PSTR + n] = make_float2(c[2], c[3]);
        }
    }
    dsum += __shfl_down_sync(0xffffffffu, dsum, 8);
    dsum += __shfl_down_sync(0xffffffffu, dsum, 4);
    dsum += __shfl_down_sync(0xffffffffu, dsum, 2);
    dsum += __shfl_down_sync(0xffffffffu, dsum, 1);
    if (cc == 0) sf[OFF_DEN + r] = dsum;     // lanes 0 and 16
    __syncthreads();

    // ---- reduce 8 partials + FiLM + store (4 outputs/thread) ----
    {
        const int m  = t >> 4;
        const int n0 = (t & 15) * 4;
        const float inv = 1.0f / sf[OFF_DEN + m];
        const float gm  = g_gamma[i0 + m];
        const float bt  = g_beta[i0 + m];
        float sx = 0.f, sy = 0.f, sz = 0.f, sw = 0.f;
#pragma unroll
        for (int w = 0; w < 8; w++) {
            const float4 p = *(const float4*)&sf[w * (64 * PSTR) + m * PSTR + n0];
            sx += p.x; sy += p.y; sz += p.z; sw += p.w;
        }
        *(float4*)(out + (size_t)(i0 + m) * OUT_F + n0) =
            make_float4(fmaf(gm, sx * inv, bt), fmaf(gm, sy * inv, bt),
                        fmaf(gm, sz * inv, bt), fmaf(gm, sw * inv, bt));
    }
}

// ============================================================================
extern "C" void kernel_launch(void* const* d_in, const int* in_sizes, int n_in,
                              void* d_out, int out_size)
{
    const float* x   = (const float*)d_in[0];
    const int*   adj = (const int*)d_in[1];
    const float* W   = (const float*)d_in[2];
    const float* a_i = (const float*)d_in[3];
    const float* a_j = (const float*)d_in[4];
    const float* w_g = (const float*)d_in[5];
    const float* w_b = (const float*)d_in[6];
    float* out = (float*)d_out;

    cudaFuncSetAttribute(prep_kernel, cudaFuncAttributeMaxDynamicSharedMemorySize, PREP_SMEM);
    cudaFuncSetAttribute(attn_kernel, cudaFuncAttributeMaxDynamicSharedMemorySize, ATTN_SMEM);

    prep_kernel<<<NN / 32, 512, PREP_SMEM>>>(x, W, a_i, a_j, w_g, w_b);
    attn_kernel<<<NN / 64, 1024, ATTN_SMEM>>>(adj, out);
}

// round 9
// speedup vs baseline: 1.3878x; 1.3271x over previous
#include <cuda_runtime.h>
#include <cstdint>

#define NN 8192
#define IN_F 256
#define OUT_F 64
#define LEAK 0.2f

// ---------------- scratch (device globals; no runtime allocation) ----------
__device__ float  g_h[NN * OUT_F];     // tf32-rounded h, row-major [j][f]
__device__ float4 g_rowEFG[NN];        // (exp(si), exp(.2 si), -, -)
__device__ float2 g_ef[NN];            // (exp(sj), exp(.2 sj))
__device__ float  g_gamma[NN];
__device__ float  g_beta[NN];

// ---------------- helpers ---------------------------------------------------
__device__ __forceinline__ float to_tf32(float x) {
    uint32_t u;
    asm("cvt.rna.tf32.f32 %0, %1;" : "=r"(u) : "f"(x));
    return __uint_as_float(u);
}

__device__ __forceinline__ uint32_t smem_u32(const void* p) {
    uint32_t a;
    asm("{ .reg .u64 t; cvta.to.shared.u64 t, %1; cvt.u32.u64 %0, t; }"
        : "=r"(a) : "l"(p));
    return a;
}

__device__ __forceinline__ void mma_tf32(float& c0, float& c1, float& c2, float& c3,
                                         uint32_t a0, uint32_t a1, uint32_t a2, uint32_t a3,
                                         uint32_t b0, uint32_t b1)
{
    asm volatile("mma.sync.aligned.m16n8k8.row.col.f32.tf32.tf32.f32 "
                 "{%0,%1,%2,%3}, {%4,%5,%6,%7}, {%8,%9}, {%0,%1,%2,%3};"
                 : "+f"(c0), "+f"(c1), "+f"(c2), "+f"(c3)
                 : "r"(a0), "r"(a1), "r"(a2), "r"(a3), "r"(b0), "r"(b1));
}

#define CP_ASYNC16(dst, src) \
    asm volatile("cp.async.cg.shared.global [%0], [%1], 16;" :: "r"(dst), "l"(src) : "memory")
#define CP_COMMIT() asm volatile("cp.async.commit_group;" ::: "memory")
#define CP_WAIT0()  asm volatile("cp.async.wait_group 0;" ::: "memory")

// ============================================================================
// Kernel 1: h = x @ W ; E/F factors, gamma, beta ; g_h tf32-rounded
// 256 blocks x 512 threads, 32 rows/block (2 blocks/SM).  (unchanged, ~23us)
// ============================================================================
#define XSTR 260
#define PREP_SMEM ((IN_F * OUT_F + 32 * XSTR + 4 * OUT_F) * 4)

__global__ __launch_bounds__(512, 2) void prep_kernel(
    const float* __restrict__ x, const float* __restrict__ W,
    const float* __restrict__ a_i, const float* __restrict__ a_j,
    const float* __restrict__ w_g, const float* __restrict__ w_b)
{
    extern __shared__ float sm[];
    float* Ws = sm;                          // [256][64] (float4-read)
    float* xs = Ws + IN_F * OUT_F;           // [32][XSTR]
    float* vs = xs + 32 * XSTR;              // 4 x [64]

    const int t = threadIdx.x;
    const int row0 = blockIdx.x * 32;

    for (int i = t; i < IN_F * OUT_F / 4; i += 512)
        ((float4*)Ws)[i] = ((const float4*)W)[i];
    for (int c = t; c < 32 * 64; c += 512) {
        const int row = c >> 6, k4 = c & 63;
        *(float4*)&xs[row * XSTR + k4 * 4] =
            ((const float4*)(x + (size_t)(row0 + row) * IN_F))[k4];
    }
    if (t < OUT_F) {
        vs[t]             = a_i[t];
        vs[OUT_F + t]     = a_j[t];
        vs[2 * OUT_F + t] = w_g[t];
        vs[3 * OUT_F + t] = w_b[t];
    }
    __syncthreads();

    const int row = t >> 4;        // 0..31
    const int fg  = t & 15;        // 0..15
    const int f0  = fg * 4;

    float4 acc = make_float4(0.f, 0.f, 0.f, 0.f);
    const float*  xr  = xs + row * XSTR;
    const float4* Ws4 = (const float4*)Ws;
#pragma unroll 8
    for (int k = 0; k < IN_F; k++) {
        const float xv = xr[k];
        const float4 w4 = Ws4[k * 16 + fg];
        acc.x = fmaf(xv, w4.x, acc.x);
        acc.y = fmaf(xv, w4.y, acc.y);
        acc.z = fmaf(xv, w4.z, acc.z);
        acc.w = fmaf(xv, w4.w, acc.w);
    }

    const int grow = row0 + row;
    *(float4*)(g_h + (size_t)grow * OUT_F + f0) =
        make_float4(to_tf32(acc.x), to_tf32(acc.y), to_tf32(acc.z), to_tf32(acc.w));

    float psi = acc.x * vs[f0]     + acc.y * vs[f0 + 1]     + acc.z * vs[f0 + 2]     + acc.w * vs[f0 + 3];
    float psj = acc.x * vs[64+f0]  + acc.y * vs[64+f0 + 1]  + acc.z * vs[64+f0 + 2]  + acc.w * vs[64+f0 + 3];
    float pg  = acc.x * vs[128+f0] + acc.y * vs[128+f0 + 1] + acc.z * vs[128+f0 + 2] + acc.w * vs[128+f0 + 3];
    float pb  = acc.x * vs[192+f0] + acc.y * vs[192+f0 + 1] + acc.z * vs[192+f0 + 2] + acc.w * vs[192+f0 + 3];
#pragma unroll
    for (int off = 8; off > 0; off >>= 1) {
        psi += __shfl_down_sync(0xffffffffu, psi, off, 16);
        psj += __shfl_down_sync(0xffffffffu, psj, off, 16);
        pg  += __shfl_down_sync(0xffffffffu, pg,  off, 16);
        pb  += __shfl_down_sync(0xffffffffu, pb,  off, 16);
    }
    if (fg == 0) {
        g_rowEFG[grow] = make_float4(__expf(psi), __expf(LEAK * psi), 0.f, 0.f);
        g_ef[grow]     = make_float2(__expf(psj), __expf(LEAK * psj));
        g_gamma[grow]  = pg + 1.0f;
        g_beta[grow]   = pb;
    }
}

// ============================================================================
// Kernel 2: fused masked softmax-attention via mma.sync tf32 + FiLM.
// 128 blocks x 1024 threads (32 warps). Block = 64 rows, j-tile BN=128.
// NO w tile: each mma warp generates its A-fragments in registers from the
// staged adj tile + E/F factors. One barrier per tile; gen+mma fused per warp.
// Warp grid: kh = wid&7 (K-eighth) x mh = wid>>3 (M-quarter); 32 accums.
// ============================================================================
#define BN   128
#define ASTR 132
#define HSTR 72
#define PSTR 68

#define OFF_H    0                       // 2 x 128 x 72 = 18432 floats
#define OFF_ADJ  18432                   // 2 x 64 x 132 = 16896 (ints)
#define OFF_EF   35328                   // 2 x 128 x 2 = 512
#define OFF_DENP 35840                   // 8 x 64 = 512
#define SMEM_FLOATS 36352
#define ATTN_SMEM (SMEM_FLOATS * 4)      // 145408 B
// epilogue partials [8][64][68] = 34816 floats overlay at offset 0 (< OFF_DENP)

__global__ __launch_bounds__(1024, 1) void attn_kernel(
    const int* __restrict__ adj, float* __restrict__ out)
{
    extern __shared__ float sf[];
    const uint32_t sbase = smem_u32(sf);

    const int t    = threadIdx.x;
    const int lane = t & 31;
    const int wid  = t >> 5;
    const int g    = lane >> 2;   // mma groupID
    const int tg   = lane & 3;    // mma threadID-in-group
    const int i0   = blockIdx.x * 64;

    const int r  = t >> 4;        // staging row 0..63
    const int cc = t & 15;        // staging chunk lane 0..15

    const int kh = wid & 7;       // K-eighth
    const int mh = wid >> 3;      // M-quarter (16 rows)

    const int m0 = mh * 16 + g;   // this thread's two w rows
    const int m1 = m0 + 8;
    const float4 efg0 = g_rowEFG[i0 + m0];
    const float4 efg1 = g_rowEFG[i0 + m1];
    const float Ei0 = efg0.x, Fi0 = efg0.y;
    const float Ei1 = efg1.x, Fi1 = efg1.y;

    const char* adj_row = (const char*)(adj + (size_t)(i0 + r) * NN);

    // hoisted staging addresses (bytes)
    const uint32_t adj_dst0 = sbase + (OFF_ADJ + r * ASTR + cc * 4) * 4;
    const int hc  = t;
    const int hk0 = hc >> 4,          hn0 = hc & 15;
    const int hk1 = (hc + 1024) >> 4, hn1 = (hc + 1024) & 15;
    const uint32_t h_dst0 = sbase + (OFF_H + hk0 * HSTR + hn0 * 4) * 4;
    const uint32_t h_dst1 = sbase + (OFF_H + hk1 * HSTR + hn1 * 4) * 4;
    const uint32_t ef_dst = sbase + (OFF_EF + t * 4) * 4;   // t<64 only
    const uint32_t ADJ_BUFB = 64 * ASTR * 4;
    const uint32_t H_BUFB   = 128 * HSTR * 4;
    const uint32_t EF_BUFB  = 256 * 4;

    // ---- prologue: tile 0 (adj, h, EF) via cp.async ----
    {
        CP_ASYNC16(adj_dst0,           adj_row + cc * 16);
        CP_ASYNC16(adj_dst0 + 16 * 16, adj_row + (cc + 16) * 16);
        CP_ASYNC16(h_dst0, (const char*)g_h + hc * 16);
        CP_ASYNC16(h_dst1, (const char*)g_h + (hc + 1024) * 16);
        if (t < 64) CP_ASYNC16(ef_dst, (const char*)g_ef + t * 16);
        CP_COMMIT();
    }

    float acc[8][4];
#pragma unroll
    for (int b = 0; b < 8; b++)
#pragma unroll
        for (int c = 0; c < 4; c++) acc[b][c] = 0.0f;
    float dsum0 = 0.0f, dsum1 = 0.0f;

    for (int tile = 0; tile < NN / BN; tile++) {
        const int buf = tile & 1;
        CP_WAIT0();
        __syncthreads();   // tile data ready; prev tile's reads complete

        // ---- prefetch next tile ----
        if (tile + 1 < NN / BN) {
            const uint32_t nb = (buf ^ 1);
            const int j1 = (tile + 1) * BN;
            const char* asrc = adj_row + (size_t)j1 * 4;
            CP_ASYNC16(adj_dst0 + nb * ADJ_BUFB,           asrc + cc * 16);
            CP_ASYNC16(adj_dst0 + nb * ADJ_BUFB + 16 * 16, asrc + (cc + 16) * 16);
            const char* hsrc = (const char*)(g_h + (size_t)j1 * OUT_F);
            CP_ASYNC16(h_dst0 + nb * H_BUFB, hsrc + hc * 16);
            CP_ASYNC16(h_dst1 + nb * H_BUFB, hsrc + (hc + 1024) * 16);
            if (t < 64) CP_ASYNC16(ef_dst + nb * EF_BUFB,
                                   (const char*)(g_ef + j1) + t * 16);
            CP_COMMIT();
        }

        // ---- fused gen + mma (per-warp; no further barriers this tile) ----
        const int*      adjS = (const int*)(sf + OFF_ADJ + buf * 64 * ASTR);
        const float2*   efS  = (const float2*)(sf + OFF_EF + buf * 256);
        const uint32_t* hsu  = (const uint32_t*)(sf + OFF_H + buf * 128 * HSTR);

#pragma unroll
        for (int kc = 0; kc < 2; kc++) {
            const int k0 = kh * 16 + kc * 8;
            const int kA = k0 + tg;
            const int kB = kA + 4;
            const float2 efA = efS[kA];
            const float2 efB = efS[kB];
            const int a00 = adjS[m0 * ASTR + kA];
            const int a10 = adjS[m1 * ASTR + kA];
            const int a01 = adjS[m0 * ASTR + kB];
            const int a11 = adjS[m1 * ASTR + kB];

            float w00, w10, w01, w11;
            { const float p = Ei0 * efA.x; const float q = Fi0 * efA.y;
              w00 = (p > 1.0f) ? p : q; w00 = a00 ? w00 : 0.0f; }
            { const float p = Ei1 * efA.x; const float q = Fi1 * efA.y;
              w10 = (p > 1.0f) ? p : q; w10 = a10 ? w10 : 0.0f; }
            { const float p = Ei0 * efB.x; const float q = Fi0 * efB.y;
              w01 = (p > 1.0f) ? p : q; w01 = a01 ? w01 : 0.0f; }
            { const float p = Ei1 * efB.x; const float q = Fi1 * efB.y;
              w11 = (p > 1.0f) ? p : q; w11 = a11 ? w11 : 0.0f; }

            dsum0 += w00 + w01;
            dsum1 += w10 + w11;

            const uint32_t ka0 = __float_as_uint(to_tf32(w00));
            const uint32_t ka1 = __float_as_uint(to_tf32(w10));
            const uint32_t ka2 = __float_as_uint(to_tf32(w01));
            const uint32_t ka3 = __float_as_uint(to_tf32(w11));

#pragma unroll
            for (int nt = 0; nt < 8; nt++) {
                const uint32_t b0 = hsu[kA * HSTR + nt * 8 + g];
                const uint32_t b1 = hsu[kB * HSTR + nt * 8 + g];
                float* c = acc[nt];
                mma_tf32(c[0], c[1], c[2], c[3], ka0, ka1, ka2, ka3, b0, b1);
            }
        }
    }

    __syncthreads();   // all warps done with smem tiles

    // ---- denominators: reduce over tg lanes (groups of 4), stage per kh ----
    dsum0 += __shfl_down_sync(0xffffffffu, dsum0, 2, 4);
    dsum0 += __shfl_down_sync(0xffffffffu, dsum0, 1, 4);
    dsum1 += __shfl_down_sync(0xffffffffu, dsum1, 2, 4);
    dsum1 += __shfl_down_sync(0xffffffffu, dsum1, 1, 4);
    if (tg == 0) {
        sf[OFF_DENP + kh * 64 + m0] = dsum0;
        sf[OFF_DENP + kh * 64 + m1] = dsum1;
    }

    // ---- stage K-split output partials (overlay on tile smem) ----
    {
        float* part = sf + kh * (64 * PSTR);
#pragma unroll
        for (int nt = 0; nt < 8; nt++) {
            const float* c = acc[nt];
            const int n = nt * 8 + tg * 2;
            *(float2*)&part[m0 * PSTR + n] = make_float2(c[0], c[1]);
            *(float2*)&part[m1 * PSTR + n] = make_float2(c[2], c[3]);
        }
    }
    __syncthreads();

    // ---- reduce 8 partials + FiLM + store (4 outputs/thread) ----
    {
        const int m  = t >> 4;
        const int n0 = (t & 15) * 4;
        float den = 0.f;
#pragma unroll
        for (int w = 0; w < 8; w++) den += sf[OFF_DENP + w * 64 + m];
        const float inv = 1.0f / den;
        const float gm  = g_gamma[i0 + m];
        const float bt  = g_beta[i0 + m];
        float sx = 0.f, sy = 0.f, sz = 0.f, sw = 0.f;
#pragma unroll
        for (int w = 0; w < 8; w++) {
            const float4 p = *(const float4*)&sf[w * (64 * PSTR) + m * PSTR + n0];
            sx += p.x; sy += p.y; sz += p.z; sw += p.w;
        }
        *(float4*)(out + (size_t)(i0 + m) * OUT_F + n0) =
            make_float4(fmaf(gm, sx * inv, bt), fmaf(gm, sy * inv, bt),
                        fmaf(gm, sz * inv, bt), fmaf(gm, sw * inv, bt));
    }
}

// ============================================================================
extern "C" void kernel_launch(void* const* d_in, const int* in_sizes, int n_in,
                              void* d_out, int out_size)
{
    const float* x   = (const float*)d_in[0];
    const int*   adj = (const int*)d_in[1];
    const float* W   = (const float*)d_in[2];
    const float* a_i = (const float*)d_in[3];
    const float* a_j = (const float*)d_in[4];
    const float* w_g = (const float*)d_in[5];
    const float* w_b = (const float*)d_in[6];
    float* out = (float*)d_out;

    cudaFuncSetAttribute(prep_kernel, cudaFuncAttributeMaxDynamicSharedMemorySize, PREP_SMEM);
    cudaFuncSetAttribute(attn_kernel, cudaFuncAttributeMaxDynamicSharedMemorySize, ATTN_SMEM);

    prep_kernel<<<NN / 32, 512, PREP_SMEM>>>(x, W, a_i, a_j, w_g, w_b);
    attn_kernel<<<NN / 64, 1024, ATTN_SMEM>>>(adj, out);
}